// round 5
// baseline (speedup 1.0000x reference)
#include <cuda_runtime.h>
#include <cuda_bf16.h>
#include <string.h>

#define HEADS  8
#define DIM    64
#define DKH    32
#define KNB    16
#define PC     (HEADS * DIM)   // 512 floats of P per row
#define RB     16              // rows per fused tile

typedef unsigned long long ull;

// M[h][d][e] = sum_k WQ[h][d][k]*WK[h][e][k]  (256B-aligned: read as 64-bit)
__device__ __align__(256) float g_M[HEADS * DIM * DIM];
__device__ int g_idx_is64;

// Packed fp32x2 ops (Blackwell sm_103a)
#define FMA_F32X2(d_, a_, b_, c_) \
    asm("fma.rn.f32x2 %0, %1, %2, %3;" : "=l"(d_) : "l"(a_), "l"(b_), "l"(c_))
#define ADD_F32X2_(d_, a_, b_) \
    asm("add.rn.f32x2 %0, %1, %2;" : "=l"(d_) : "l"(a_), "l"(b_))

__device__ __forceinline__ ull dup_f32(float v) {
    unsigned u = __float_as_uint(v);
    return ((ull)u << 32) | (ull)u;
}
__device__ __forceinline__ float sum2(ull p) {
    float2 v; memcpy(&v, &p, 8);
    return v.x + v.y;
}

// ---------------------------------------------------------------------------
// Kernel 0: M[h] = WQ[h] @ WK[h]^T. Grid 64 = 8 heads x 8 d-groups (round-4
// profile showed grid=8 was latency-bound at 16us). Also probes idx dtype
// (int64 values < 2^31 have zero high words).
// ---------------------------------------------------------------------------
__global__ void __launch_bounds__(256)
gar_build_m(const float* __restrict__ WQ,
            const float* __restrict__ WK,
            const void*  __restrict__ idx_raw) {
    __shared__ float sk[DIM * DKH];   // WK[h], 8 KB
    __shared__ float sq[8 * DKH];     // 8 rows of WQ[h]
    const int h  = blockIdx.x >> 3;
    const int dg = blockIdx.x & 7;    // d-group: rows [8dg, 8dg+8)
    const int t  = threadIdx.x;

    if (blockIdx.x == 0 && t == 0) {
        const int* p = (const int*)idx_raw;
        int any = 0;
        #pragma unroll
        for (int j = 0; j < 32; ++j) any |= p[2 * j + 1];
        g_idx_is64 = (any == 0) ? 1 : 0;
    }

    #pragma unroll
    for (int i = t; i < DIM * DKH; i += 256) sk[i] = WK[h * DIM * DKH + i];
    if (t < 8 * DKH) sq[t] = WQ[h * DIM * DKH + dg * 8 * DKH + t];
    __syncthreads();

    #pragma unroll
    for (int p = 0; p < 2; ++p) {
        const int o  = p * 256 + t;       // 0..511
        const int dd = o >> 6, e = o & 63;
        float s = 0.f;
        #pragma unroll
        for (int k = 0; k < DKH; ++k)
            s += sq[dd * DKH + k] * sk[e * DKH + k];
        g_M[h * DIM * DIM + (dg * 8 + dd) * DIM + e] = s;
    }
}

// ---------------------------------------------------------------------------
// Fused kernel: persistent blocks, 16-row tiles.
//  Phase A: stage Z tile in shared, pre-duplicated as (z,z) b64 pairs.
//  Phase B: P[r][c] = Z[r] . M[:, c] — thread t owns columns (2t, 2t+1);
//           W pair resident in 64 b64 regs, loaded ONCE per block.
//           Inner loop: broadcast LDS.128 -> 2 FFMA2 (crossbar vs FMA balance).
//           P tile written to shared (no g_P global round-trip at all).
//  Phase C: attention. Warp w handles tile rows w, w+8. Lane l: head l>>2,
//           segment s=l&3 -> P floats [16l,16l+16) from shared, Z floats
//           [16s,16s+16) gathered from the (now L2-resident) 25.6MB Z table.
//           xor{1,2} completes head dots; register softmax over K=16;
//           xor{4,8,16} head mean; EMA blend + clamp.
// ---------------------------------------------------------------------------
__global__ void __launch_bounds__(256, 1)
gar_fused(const float* __restrict__ Z,
          const float* __restrict__ f,
          const void*  __restrict__ idx_raw,
          const float* __restrict__ ema,
          float* __restrict__ out,
          int N, int ntiles) {
    __shared__ __align__(16) ull   zdup[RB * DIM];   // 8 KB
    __shared__ __align__(16) float Psh[RB * PC];     // 32 KB
    const int t    = threadIdx.x;
    const int l    = t & 31;
    const int warp = t >> 5;
    const int c0   = 2 * t;
    const int h    = c0 >> 6;
    const int e0   = c0 & 63;
    const int s    = l & 3;
    const unsigned FULL = 0xffffffffu;
    const float scale = 0.17677669529663687f;   // 1/sqrt(32)

    // W pair registers: wv[d] = (M[h][d][e0], M[h][d][e0+1]) — once per block
    ull wv[DIM];
    {
        const float* mb = g_M + h * DIM * DIM + e0;
        #pragma unroll
        for (int d = 0; d < DIM; ++d) {
            ull v; memcpy(&v, mb + d * DIM, 8);   // 8B aligned (e0 even)
            wv[d] = v;
        }
    }
    const int is64 = g_idx_is64;

    #pragma unroll 1
    for (int tile = blockIdx.x; tile < ntiles; tile += gridDim.x) {
        const int base = tile * RB;

        // ---- Phase A: stage duplicated Z tile (256 float4 = 1 per thread)
        {
            const int r  = t >> 4;
            const int d4 = (t & 15) * 4;
            const int n  = base + r;
            float4 v = (n < N) ? *(const float4*)(Z + (size_t)n * DIM + d4)
                               : make_float4(0.f, 0.f, 0.f, 0.f);
            ulonglong2 p0, p1;
            p0.x = dup_f32(v.x); p0.y = dup_f32(v.y);
            p1.x = dup_f32(v.z); p1.y = dup_f32(v.w);
            ulonglong2* z2 = (ulonglong2*)zdup;
            z2[r * (DIM / 2) + (d4 >> 1)]     = p0;
            z2[r * (DIM / 2) + (d4 >> 1) + 1] = p1;
        }
        __syncthreads();

        // ---- Phase B: GEMM rows of this tile
        #pragma unroll 1
        for (int r = 0; r < RB; ++r) {
            const ulonglong2* zr = (const ulonglong2*)(zdup + r * DIM);
            ull a0 = 0, a1 = 0, a2 = 0, a3 = 0;
            #pragma unroll
            for (int q = 0; q < 32; q += 2) {
                ulonglong2 v0 = zr[q];
                ulonglong2 v1 = zr[q + 1];
                FMA_F32X2(a0, v0.x, wv[2 * q + 0], a0);
                FMA_F32X2(a1, v0.y, wv[2 * q + 1], a1);
                FMA_F32X2(a2, v1.x, wv[2 * q + 2], a2);
                FMA_F32X2(a3, v1.y, wv[2 * q + 3], a3);
            }
            ADD_F32X2_(a0, a0, a1);
            ADD_F32X2_(a2, a2, a3);
            ADD_F32X2_(a0, a0, a2);
            float2 res; memcpy(&res, &a0, 8);
            *(float2*)(Psh + r * PC + c0) = res;
        }
        __syncthreads();

        // ---- Phase C: attention (warp w -> tile rows w, w+8)
        #pragma unroll 1
        for (int rr = warp; rr < RB; rr += 8) {
            const int i = base + rr;
            if (i < N) {
                // P segment from shared: 16 floats = 8 packed pairs
                ull pp[8];
                {
                    const ulonglong2* pb =
                        (const ulonglong2*)(Psh + rr * PC + l * 16);
                    #pragma unroll
                    for (int q = 0; q < 4; ++q) {
                        ulonglong2 v = pb[q];
                        pp[2 * q] = v.x; pp[2 * q + 1] = v.y;
                    }
                }

                long long nj_l = 0;
                float fn_l = 0.f;
                if (l < KNB) {
                    if (is64)
                        nj_l = ((const long long*)idx_raw)[(size_t)i * KNB + l];
                    else
                        nj_l = (long long)((const int*)idx_raw)[(size_t)i * KNB + l];
                    fn_l = fmaxf(f[nj_l], 0.f);
                }
                const float fi = fmaxf(f[i], 0.f);

                float lg[KNB];
                #pragma unroll
                for (int j = 0; j < KNB; ++j) {
                    const long long nj = __shfl_sync(FULL, nj_l, j);
                    const ulonglong2* zb =
                        (const ulonglong2*)(Z + (size_t)nj * DIM + s * 16);
                    ull a0 = 0, a1 = 0;
                    #pragma unroll
                    for (int q = 0; q < 4; ++q) {
                        ulonglong2 zv = zb[q];
                        FMA_F32X2(a0, zv.x, pp[2 * q], a0);
                        FMA_F32X2(a1, zv.y, pp[2 * q + 1], a1);
                    }
                    ADD_F32X2_(a0, a0, a1);
                    float p = sum2(a0);
                    p += __shfl_xor_sync(FULL, p, 1);
                    p += __shfl_xor_sync(FULL, p, 2);
                    const float fj = __shfl_sync(FULL, fn_l, j);
                    lg[j] = p * scale - 0.5f * (fi + fj);  // GAMMA=0.5, TAU=1
                }

                // Softmax over 16 neighbors (per head; replicated over s-lanes)
                float mx = lg[0];
                #pragma unroll
                for (int j = 1; j < KNB; ++j) mx = fmaxf(mx, lg[j]);
                float ssum = 0.f;
                #pragma unroll
                for (int j = 0; j < KNB; ++j) {
                    float e = __expf(lg[j] - mx); lg[j] = e; ssum += e;
                }
                const float inv = 1.f / ssum;
                #pragma unroll
                for (int j = 0; j < KNB; ++j) lg[j] *= inv;

                // Sum over 8 heads: lanes {s, s+4, ..., s+28}
                #pragma unroll
                for (int off = 4; off < 32; off <<= 1) {
                    #pragma unroll
                    for (int j = 0; j < KNB; ++j)
                        lg[j] += __shfl_xor_sync(FULL, lg[j], off);
                }

                if (l < KNB) {
                    float wv2 = lg[0];
                    #pragma unroll
                    for (int j = 1; j < KNB; ++j) if (l == j) wv2 = lg[j];
                    const float wattn = wv2 * (1.f / HEADS);
                    const float o = 0.9f * ema[(size_t)i * KNB + l] + 0.1f * wattn;
                    out[(size_t)i * KNB + l] = fmaxf(o, 0.f);
                }
            }
        }
        __syncthreads();   // protect zdup/Psh before next tile
    }
}

// ---------------------------------------------------------------------------
extern "C" void kernel_launch(void* const* d_in, const int* in_sizes, int n_in,
                              void* d_out, int out_size) {
    const float* Z   = (const float*)d_in[0];   // [N, 64]
    const float* f   = (const float*)d_in[1];   // [N]
    const float* WQ  = (const float*)d_in[2];   // [8, 64, 32]
    const float* WK  = (const float*)d_in[3];   // [8, 64, 32]
    const float* ema = (const float*)d_in[4];   // [N, 16]
    const void*  idx = (const void*)d_in[5];    // [N, 16] int64 or int32
    float* out = (float*)d_out;

    const int N = in_sizes[0] / DIM;
    const int ntiles = (N + RB - 1) / RB;

    gar_build_m<<<64, 256>>>(WQ, WK, idx);
    gar_fused<<<148, 256>>>(Z, f, idx, ema, out, N, ntiles);
}